// round 1
// baseline (speedup 1.0000x reference)
#include <cuda_runtime.h>

// Problem constants
#define BB      2
#define CC      512
#define HWN     4096
#define GG      32
#define CGN     16            // channels per group
#define NHEADS  8
#define DHD     64
#define EPSV    1e-5f
#define QSCALE  0.35355339059327373f   // 64^-0.25

#define MTOT    (BB * HWN)    // 8192 rows for the token-major matrices

// Scratch (device globals; no allocation allowed)
__device__ float g_t[(size_t)MTOT * CC];   // normalized, transposed input (B,HW,C)
__device__ float g_q[(size_t)MTOT * CC];
__device__ float g_k[(size_t)MTOT * CC];
__device__ float g_v[(size_t)MTOT * CC];
__device__ float g_o[(size_t)MTOT * CC];   // attention output (B,HW,C)
__device__ float g_mean[BB * GG];
__device__ float g_rstd[BB * GG];

// ---------------------------------------------------------------------------
// Kernel 1: GroupNorm statistics. One block per (b,g); the group's data is a
// contiguous span of CGN*HWN floats.
// ---------------------------------------------------------------------------
__global__ void gn_stats_kernel(const float* __restrict__ x) {
    int bg = blockIdx.x;
    const float4* p4 = (const float4*)(x + (size_t)bg * CGN * HWN);
    const int n4 = CGN * HWN / 4;   // 16384
    float s = 0.f, ss = 0.f;
    for (int i = threadIdx.x; i < n4; i += blockDim.x) {
        float4 v = p4[i];
        s  += (v.x + v.y) + (v.z + v.w);
        ss += v.x * v.x + v.y * v.y + v.z * v.z + v.w * v.w;
    }
    #pragma unroll
    for (int off = 16; off; off >>= 1) {
        s  += __shfl_xor_sync(0xffffffffu, s, off);
        ss += __shfl_xor_sync(0xffffffffu, ss, off);
    }
    __shared__ float shs[8], shss[8];
    int w = threadIdx.x >> 5, lane = threadIdx.x & 31;
    if (lane == 0) { shs[w] = s; shss[w] = ss; }
    __syncthreads();
    if (threadIdx.x == 0) {
        s = 0.f; ss = 0.f;
        #pragma unroll
        for (int i = 0; i < 8; i++) { s += shs[i]; ss += shss[i]; }
        const float inv_n = 1.0f / (float)(CGN * HWN);
        float mean = s * inv_n;
        float var  = ss * inv_n - mean * mean;
        g_mean[bg] = mean;
        g_rstd[bg] = rsqrtf(var + EPSV);
    }
}

// ---------------------------------------------------------------------------
// Kernel 2: apply GroupNorm affine + transpose (B,C,HW) -> (B,HW,C) into g_t.
// 32x32 shared tile, coalesced reads and writes.
// ---------------------------------------------------------------------------
__global__ void gn_apply_kernel(const float* __restrict__ x,
                                const float* __restrict__ gw,
                                const float* __restrict__ gb) {
    __shared__ float tile[32][33];
    int hw0 = blockIdx.x * 32, c0 = blockIdx.y * 32, b = blockIdx.z;
    int tx = threadIdx.x, ty = threadIdx.y;
    #pragma unroll
    for (int i = 0; i < 4; i++) {
        int c = c0 + ty + i * 8;
        tile[ty + i * 8][tx] = x[((size_t)b * CC + c) * HWN + hw0 + tx];
    }
    __syncthreads();
    #pragma unroll
    for (int i = 0; i < 4; i++) {
        int hw = hw0 + ty + i * 8;
        int c  = c0 + tx;
        int bg = b * GG + (c >> 4);
        float v = tile[tx][ty + i * 8];
        g_t[((size_t)b * HWN + hw) * CC + c] =
            (v - g_mean[bg]) * g_rstd[bg] * gw[c] + gb[c];
    }
}

// ---------------------------------------------------------------------------
// Kernel 3: tiled fp32 GEMM.  out[m][n] = alpha*(sum_k A[m][k]*W[n][k] + bias[n])
// A: [MTOT][CC] row-major, W: [CC][CC] row-major (weight, k contiguous).
// trans_residual=1: write transposed to (B,C,HW) layout with +bias +residual.
// Tiles: BM=BN=64, BK=16; 256 threads; 4x4 microtile with stride-16 mapping
// (conflict-free smem reads on the Ws side, broadcast on the As side).
// ---------------------------------------------------------------------------
__global__ void __launch_bounds__(256) gemm_kernel(
        const float* __restrict__ A, const float* __restrict__ W,
        const float* __restrict__ bias, float* __restrict__ out,
        float alpha, int trans_residual, const float* __restrict__ resid) {
    __shared__ float As[64][17];
    __shared__ float Ws[64][17];
    const int m0 = blockIdx.x * 64, n0 = blockIdx.y * 64;
    const int tid = threadIdx.x;
    const int tx = tid & 15, ty = tid >> 4;
    const int lr  = tid >> 2;          // 0..63 tile row for loads
    const int lk4 = (tid & 3) << 2;    // 0,4,8,12

    float acc[4][4] = {};

    for (int kt = 0; kt < CC; kt += 16) {
        float4 av = *(const float4*)(A + (size_t)(m0 + lr) * CC + kt + lk4);
        float4 wv = *(const float4*)(W + (size_t)(n0 + lr) * CC + kt + lk4);
        As[lr][lk4 + 0] = av.x; As[lr][lk4 + 1] = av.y;
        As[lr][lk4 + 2] = av.z; As[lr][lk4 + 3] = av.w;
        Ws[lr][lk4 + 0] = wv.x; Ws[lr][lk4 + 1] = wv.y;
        Ws[lr][lk4 + 2] = wv.z; Ws[lr][lk4 + 3] = wv.w;
        __syncthreads();
        #pragma unroll
        for (int kk = 0; kk < 16; kk++) {
            float a[4], bb[4];
            #pragma unroll
            for (int i = 0; i < 4; i++) a[i] = As[ty + 16 * i][kk];
            #pragma unroll
            for (int j = 0; j < 4; j++) bb[j] = Ws[tx + 16 * j][kk];
            #pragma unroll
            for (int i = 0; i < 4; i++)
                #pragma unroll
                for (int j = 0; j < 4; j++)
                    acc[i][j] += a[i] * bb[j];
        }
        __syncthreads();
    }

    if (!trans_residual) {
        #pragma unroll
        for (int i = 0; i < 4; i++) {
            int m = m0 + ty + 16 * i;
            #pragma unroll
            for (int j = 0; j < 4; j++) {
                int n = n0 + tx + 16 * j;
                out[(size_t)m * CC + n] = alpha * (acc[i][j] + bias[n]);
            }
        }
    } else {
        #pragma unroll
        for (int i = 0; i < 4; i++) {
            int m  = m0 + ty + 16 * i;
            int b  = m >> 12;             // / HWN
            int hw = m & (HWN - 1);
            #pragma unroll
            for (int j = 0; j < 4; j++) {
                int n = n0 + tx + 16 * j;
                size_t oi = ((size_t)b * CC + n) * HWN + hw;
                out[oi] = acc[i][j] + bias[n] + resid[oi];
            }
        }
    }
}

// ---------------------------------------------------------------------------
// Kernel 4: flash attention, fp32 SIMT.
// Block = 256 threads handles one 64-query tile for one (b,h); streams 64-key
// tiles through shared memory with online softmax. Q/K pre-scaled by QSCALE
// in the QKV GEMM, so scores need no extra scaling.
// Shared rows use stride 68 floats (272B = 16B aligned, banks spread).
// ---------------------------------------------------------------------------
#define SQ 68
#define ATTN_SMEM (4 * 64 * SQ * 4)   // Qs, Ks, Vs, Ps = 69632 bytes

__global__ void __launch_bounds__(256) attn_kernel() {
    extern __shared__ float sm[];
    float* Qs = sm;
    float* Ks = sm + 64 * SQ;
    float* Vs = sm + 2 * 64 * SQ;
    float* Ps = sm + 3 * 64 * SQ;

    const int q0 = blockIdx.x * 64;
    const int h  = blockIdx.y;
    const int b  = blockIdx.z;
    const int tid = threadIdx.x;
    const int tx = tid & 15, ty = tid >> 4;

    const float* Qg = g_q + (size_t)b * HWN * CC + (size_t)h * DHD;
    const float* Kg = g_k + (size_t)b * HWN * CC + (size_t)h * DHD;
    const float* Vg = g_v + (size_t)b * HWN * CC + (size_t)h * DHD;

    // Load Q tile (64 x 64)
    #pragma unroll
    for (int it = 0; it < 4; it++) {
        int idx = tid + 256 * it;
        int r = idx >> 4, c4 = (idx & 15) << 2;
        *(float4*)(Qs + r * SQ + c4) =
            *(const float4*)(Qg + (size_t)(q0 + r) * CC + c4);
    }

    float m_[4], l_[4], o_[4][4];
    #pragma unroll
    for (int i = 0; i < 4; i++) {
        m_[i] = -1e30f; l_[i] = 0.f;
        #pragma unroll
        for (int j = 0; j < 4; j++) o_[i][j] = 0.f;
    }

    for (int kt = 0; kt < HWN; kt += 64) {
        __syncthreads();   // prior-tile consumers done (also covers Q store, it 0)
        #pragma unroll
        for (int it = 0; it < 4; it++) {
            int idx = tid + 256 * it;
            int r = idx >> 4, c4 = (idx & 15) << 2;
            *(float4*)(Ks + r * SQ + c4) =
                *(const float4*)(Kg + (size_t)(kt + r) * CC + c4);
            *(float4*)(Vs + r * SQ + c4) =
                *(const float4*)(Vg + (size_t)(kt + r) * CC + c4);
        }
        __syncthreads();

        // S = Q @ K^T  (rows ty+16i, cols tx+16j)
        float s[4][4] = {};
        #pragma unroll
        for (int d = 0; d < 64; d += 4) {
            float4 a[4], kb[4];
            #pragma unroll
            for (int i = 0; i < 4; i++)
                a[i] = *(const float4*)(Qs + (ty + 16 * i) * SQ + d);
            #pragma unroll
            for (int j = 0; j < 4; j++)
                kb[j] = *(const float4*)(Ks + (tx + 16 * j) * SQ + d);
            #pragma unroll
            for (int i = 0; i < 4; i++)
                #pragma unroll
                for (int j = 0; j < 4; j++)
                    s[i][j] += a[i].x * kb[j].x + a[i].y * kb[j].y
                             + a[i].z * kb[j].z + a[i].w * kb[j].w;
        }

        // online softmax (rows shared by the 16 lanes of a half-warp)
        float p[4][4];
        #pragma unroll
        for (int i = 0; i < 4; i++) {
            float tm = fmaxf(fmaxf(s[i][0], s[i][1]), fmaxf(s[i][2], s[i][3]));
            #pragma unroll
            for (int off = 8; off; off >>= 1)
                tm = fmaxf(tm, __shfl_xor_sync(0xffffffffu, tm, off));
            float mn = fmaxf(m_[i], tm);
            float f  = __expf(m_[i] - mn);
            m_[i] = mn;
            float sum = 0.f;
            #pragma unroll
            for (int j = 0; j < 4; j++) {
                p[i][j] = __expf(s[i][j] - mn);
                sum += p[i][j];
            }
            #pragma unroll
            for (int off = 8; off; off >>= 1)
                sum += __shfl_xor_sync(0xffffffffu, sum, off);
            l_[i] = l_[i] * f + sum;
            #pragma unroll
            for (int j = 0; j < 4; j++) o_[i][j] *= f;
        }

        // stage P, then O += P @ V (rows ty+16i, dcols tx+16j)
        #pragma unroll
        for (int i = 0; i < 4; i++)
            #pragma unroll
            for (int j = 0; j < 4; j++)
                Ps[(ty + 16 * i) * SQ + tx + 16 * j] = p[i][j];
        __syncthreads();

        #pragma unroll
        for (int kk = 0; kk < 64; kk += 4) {
            float4 pr[4];
            #pragma unroll
            for (int i = 0; i < 4; i++)
                pr[i] = *(const float4*)(Ps + (ty + 16 * i) * SQ + kk);
            float vv[4][4];
            #pragma unroll
            for (int e = 0; e < 4; e++)
                #pragma unroll
                for (int j = 0; j < 4; j++)
                    vv[e][j] = Vs[(kk + e) * SQ + tx + 16 * j];
            #pragma unroll
            for (int i = 0; i < 4; i++)
                #pragma unroll
                for (int j = 0; j < 4; j++)
                    o_[i][j] += pr[i].x * vv[0][j] + pr[i].y * vv[1][j]
                              + pr[i].z * vv[2][j] + pr[i].w * vv[3][j];
        }
    }

    #pragma unroll
    for (int i = 0; i < 4; i++) {
        float inv = 1.0f / l_[i];
        #pragma unroll
        for (int j = 0; j < 4; j++)
            g_o[((size_t)b * HWN + q0 + ty + 16 * i) * CC + h * DHD + tx + 16 * j] =
                o_[i][j] * inv;
    }
}

// ---------------------------------------------------------------------------
// Launcher
// ---------------------------------------------------------------------------
extern "C" void kernel_launch(void* const* d_in, const int* in_sizes, int n_in,
                              void* d_out, int out_size) {
    const float* x  = (const float*)d_in[0];
    const float* gw = (const float*)d_in[1];
    const float* gb = (const float*)d_in[2];
    const float* wq = (const float*)d_in[3];
    const float* bq = (const float*)d_in[4];
    const float* wk = (const float*)d_in[5];
    const float* bk = (const float*)d_in[6];
    const float* wv = (const float*)d_in[7];
    const float* bv = (const float*)d_in[8];
    const float* wp = (const float*)d_in[9];
    const float* bp = (const float*)d_in[10];
    float* out = (float*)d_out;

    float *pt, *pq, *pk, *pv, *po;
    cudaGetSymbolAddress((void**)&pt, g_t);
    cudaGetSymbolAddress((void**)&pq, g_q);
    cudaGetSymbolAddress((void**)&pk, g_k);
    cudaGetSymbolAddress((void**)&pv, g_v);
    cudaGetSymbolAddress((void**)&po, g_o);

    gn_stats_kernel<<<BB * GG, 256>>>(x);
    gn_apply_kernel<<<dim3(HWN / 32, CC / 32, BB), dim3(32, 8)>>>(x, gw, gb);

    dim3 gg(MTOT / 64, CC / 64);
    gemm_kernel<<<gg, 256>>>(pt, wq, bq, pq, QSCALE, 0, nullptr);
    gemm_kernel<<<gg, 256>>>(pt, wk, bk, pk, QSCALE, 0, nullptr);
    gemm_kernel<<<gg, 256>>>(pt, wv, bv, pv, 1.0f, 0, nullptr);

    cudaFuncSetAttribute(attn_kernel,
                         cudaFuncAttributeMaxDynamicSharedMemorySize, ATTN_SMEM);
    attn_kernel<<<dim3(HWN / 64, NHEADS, BB), 256, ATTN_SMEM>>>();

    gemm_kernel<<<gg, 256>>>(po, wp, bp, out, 1.0f, 1, x);
}